// round 1
// baseline (speedup 1.0000x reference)
#include <cuda_runtime.h>
#include <cuda_bf16.h>

#define CDIM 256
#define NSEG 65536
#define NB 8
#define SPLITK 8
#define KCHUNK (NSEG / SPLITK)
#define TK 32

// scratch (allocation-free rule: __device__ globals)
__device__ float g_partial[SPLITK * NB * CDIM * CDIM]; // 16 MB
__device__ float g_attn[NB * CDIM * CDIM];             // 2 MB

typedef unsigned long long u64;

__device__ __forceinline__ u64 dup_f32(float x) {
    u64 r; asm("mov.b64 %0, {%1, %1};" : "=l"(r) : "f"(x)); return r;
}
__device__ __forceinline__ void fma_x2(u64 &d, u64 a, u64 b) {
    asm("fma.rn.f32x2 %0, %1, %2, %0;" : "+l"(d) : "l"(a), "l"(b));
}
__device__ __forceinline__ float2 unpk(u64 v) {
    float2 f; asm("mov.b64 {%0, %1}, %2;" : "=f"(f.x), "=f"(f.y) : "l"(v)); return f;
}

// ---------------------------------------------------------------------------
// Kernel 1: Gram partials. E_partial[s][b] = X[:, s-chunk] * X[:, s-chunk]^T
// 128x128 block tile, 8x8 per thread (f32x2-packed), TK=32.
// grid (4 tiles, SPLITK, NB), 256 threads.
// ---------------------------------------------------------------------------
__global__ void __launch_bounds__(256, 2) gram_kernel(const float* __restrict__ feats) {
    const int tile  = blockIdx.x;
    const int split = blockIdx.y;
    const int b     = blockIdx.z;
    const float* X  = feats + (size_t)b * CDIM * NSEG;
    const int r0 = (tile >> 1) * 128;
    const int c0 = (tile & 1) * 128;
    const int k0 = split * KCHUNK;

    __shared__ float As[TK][132];
    __shared__ float Bs[TK][132];

    const int tid = threadIdx.x;
    const int tx  = tid & 15;
    const int ty  = tid >> 4;
    const int lrow = tid >> 3;        // 0..31
    const int lk   = (tid & 7) * 4;   // 0,4,...,28

    u64 acc[8][4];
#pragma unroll
    for (int i = 0; i < 8; i++)
#pragma unroll
        for (int j = 0; j < 4; j++) acc[i][j] = 0ull;

#pragma unroll 1
    for (int kb = 0; kb < KCHUNK; kb += TK) {
        const int kg = k0 + kb + lk;
#pragma unroll
        for (int p = 0; p < 4; p++) {
            int row = p * 32 + lrow;
            float4 va = *(const float4*)(X + (size_t)(r0 + row) * NSEG + kg);
            float4 vb = *(const float4*)(X + (size_t)(c0 + row) * NSEG + kg);
            As[lk + 0][row] = va.x; As[lk + 1][row] = va.y;
            As[lk + 2][row] = va.z; As[lk + 3][row] = va.w;
            Bs[lk + 0][row] = vb.x; Bs[lk + 1][row] = vb.y;
            Bs[lk + 2][row] = vb.z; Bs[lk + 3][row] = vb.w;
        }
        __syncthreads();
#pragma unroll
        for (int kk = 0; kk < TK; kk++) {
            float4 a0 = *(const float4*)&As[kk][ty * 8];
            float4 a1 = *(const float4*)&As[kk][ty * 8 + 4];
            u64 b2[4];
#pragma unroll
            for (int jp = 0; jp < 4; jp++)
                b2[jp] = *(const u64*)&Bs[kk][tx * 8 + jp * 2];
            float av[8] = {a0.x, a0.y, a0.z, a0.w, a1.x, a1.y, a1.z, a1.w};
#pragma unroll
            for (int i = 0; i < 8; i++) {
                u64 ad = dup_f32(av[i]);
#pragma unroll
                for (int jp = 0; jp < 4; jp++) fma_x2(acc[i][jp], ad, b2[jp]);
            }
        }
        __syncthreads();
    }

    float* P = g_partial + (size_t)(split * NB + b) * CDIM * CDIM;
#pragma unroll
    for (int i = 0; i < 8; i++) {
        int r = r0 + ty * 8 + i;
#pragma unroll
        for (int jp = 0; jp < 4; jp++)
            *(u64*)(P + (size_t)r * CDIM + c0 + tx * 8 + jp * 2) = acc[i][jp];
    }
}

// ---------------------------------------------------------------------------
// Kernel 2: reduce split-k partials, row softmax of (-E), fold gamma.
// softmax(max(E)-E) == exp(min(E)-E)/sum  (shift-invariant, stable)
// grid NB*CDIM rows, 256 threads (one per column).
// ---------------------------------------------------------------------------
__global__ void softmax_kernel(const float* __restrict__ gamma) {
    const int row = blockIdx.x;   // b*256 + r
    const int d   = threadIdx.x;

    float e = 0.f;
#pragma unroll
    for (int s = 0; s < SPLITK; s++)
        e += g_partial[(size_t)s * NB * CDIM * CDIM + (size_t)row * CDIM + d];

    __shared__ float red[CDIM];
    red[d] = e;
    __syncthreads();
    for (int s = 128; s > 0; s >>= 1) {
        if (d < s) red[d] = fminf(red[d], red[d + s]);
        __syncthreads();
    }
    float minv = red[0];
    __syncthreads();

    float v = expf(minv - e);   // <= 1, no overflow
    red[d] = v;
    __syncthreads();
    for (int s = 128; s > 0; s >>= 1) {
        if (d < s) red[d] += red[d + s];
        __syncthreads();
    }
    float sum = red[0];

    g_attn[(size_t)row * CDIM + d] = gamma[0] * v / sum;
}

// ---------------------------------------------------------------------------
// Kernel 3: Y = attn' * X + X   (attn' already scaled by gamma)
// 128(c) x 128(j) block tile, k=256, 8x8 per thread (f32x2).
// grid (NSEG/128, 2, NB), 256 threads.
// ---------------------------------------------------------------------------
__global__ void __launch_bounds__(256, 2) out_kernel(const float* __restrict__ feats,
                                                     float* __restrict__ out) {
    const int b  = blockIdx.z;
    const int c0 = blockIdx.y * 128;
    const int j0 = blockIdx.x * 128;
    const float* X = feats + (size_t)b * CDIM * NSEG;
    const float* A = g_attn + (size_t)b * CDIM * CDIM;
    float* Y = out + (size_t)b * CDIM * NSEG;

    __shared__ float As2[TK][132];
    __shared__ float Xs[TK][128];

    const int tid = threadIdx.x;
    const int tx  = tid & 15;
    const int ty  = tid >> 4;
    const int lrow = tid >> 3;        // A-tile loading
    const int lk4  = (tid & 7) * 4;
    const int xk   = tid >> 5;        // X-tile loading
    const int xj   = (tid & 31) * 4;

    u64 acc[8][4];
#pragma unroll
    for (int i = 0; i < 8; i++)
#pragma unroll
        for (int j = 0; j < 4; j++) acc[i][j] = 0ull;

#pragma unroll 1
    for (int kb = 0; kb < CDIM; kb += TK) {
#pragma unroll
        for (int p = 0; p < 4; p++) {
            int c = p * 32 + lrow;
            float4 va = *(const float4*)(A + (size_t)(c0 + c) * CDIM + kb + lk4);
            As2[lk4 + 0][c] = va.x; As2[lk4 + 1][c] = va.y;
            As2[lk4 + 2][c] = va.z; As2[lk4 + 3][c] = va.w;
            int kr = p * 8 + xk;
            float4 vx = *(const float4*)(X + (size_t)(kb + kr) * NSEG + j0 + xj);
            *(float4*)&Xs[kr][xj] = vx;
        }
        __syncthreads();
#pragma unroll
        for (int kk = 0; kk < TK; kk++) {
            float4 a0 = *(const float4*)&As2[kk][ty * 8];
            float4 a1 = *(const float4*)&As2[kk][ty * 8 + 4];
            u64 b2[4];
#pragma unroll
            for (int jp = 0; jp < 4; jp++)
                b2[jp] = *(const u64*)&Xs[kk][tx * 8 + jp * 2];
            float av[8] = {a0.x, a0.y, a0.z, a0.w, a1.x, a1.y, a1.z, a1.w};
#pragma unroll
            for (int i = 0; i < 8; i++) {
                u64 ad = dup_f32(av[i]);
#pragma unroll
                for (int jp = 0; jp < 4; jp++) fma_x2(acc[i][jp], ad, b2[jp]);
            }
        }
        __syncthreads();
    }

    // epilogue: add residual X and store
#pragma unroll
    for (int i = 0; i < 8; i++) {
        int c = c0 + ty * 8 + i;
        const float* xr = X + (size_t)c * NSEG + j0 + tx * 8;
        float*       yr = Y + (size_t)c * NSEG + j0 + tx * 8;
#pragma unroll
        for (int jp = 0; jp < 4; jp++) {
            float2 v  = unpk(acc[i][jp]);
            float2 xv = *(const float2*)(xr + jp * 2);
            float2 o; o.x = v.x + xv.x; o.y = v.y + xv.y;
            *(float2*)(yr + jp * 2) = o;
        }
    }
}

// ---------------------------------------------------------------------------
extern "C" void kernel_launch(void* const* d_in, const int* in_sizes, int n_in,
                              void* d_out, int out_size) {
    const float* feats = (const float*)d_in[0];
    const float* gamma = (const float*)d_in[1];
    float* out = (float*)d_out;

    gram_kernel<<<dim3(4, SPLITK, NB), 256>>>(feats);
    softmax_kernel<<<NB * CDIM, CDIM>>>(gamma);
    out_kernel<<<dim3(NSEG / 128, CDIM / 128, NB), 256>>>(feats, out);
}

// round 2
// speedup vs baseline: 1.0008x; 1.0008x over previous
#include <cuda_runtime.h>
#include <cuda_bf16.h>

#define CDIM 256
#define NSEG 65536
#define NB 8
#define SPLITK 8
#define KCHUNK (NSEG / SPLITK)
#define TK 32

// scratch (allocation-free rule: __device__ globals)
__device__ float g_partial[SPLITK * NB * CDIM * CDIM]; // 16 MB
__device__ float g_attn[NB * CDIM * CDIM];             // 2 MB

typedef unsigned long long u64;

__device__ __forceinline__ u64 dup_f32(float x) {
    u64 r; asm("mov.b64 %0, {%1, %1};" : "=l"(r) : "f"(x)); return r;
}
__device__ __forceinline__ void fma_x2(u64 &d, u64 a, u64 b) {
    asm("fma.rn.f32x2 %0, %1, %2, %0;" : "+l"(d) : "l"(a), "l"(b));
}
__device__ __forceinline__ float2 unpk(u64 v) {
    float2 f; asm("mov.b64 {%0, %1}, %2;" : "=f"(f.x), "=f"(f.y) : "l"(v)); return f;
}

// ---------------------------------------------------------------------------
// Kernel 1: Gram partials. E_partial[s][b] = X[:, s-chunk] * X[:, s-chunk]^T
// 128x128 block tile, 8x8 per thread (f32x2-packed), TK=32.
// grid (4 tiles, SPLITK, NB), 256 threads.
// ---------------------------------------------------------------------------
__global__ void __launch_bounds__(256, 2) gram_kernel(const float* __restrict__ feats) {
    const int tile  = blockIdx.x;
    const int split = blockIdx.y;
    const int b     = blockIdx.z;
    const float* X  = feats + (size_t)b * CDIM * NSEG;
    const int r0 = (tile >> 1) * 128;
    const int c0 = (tile & 1) * 128;
    const int k0 = split * KCHUNK;

    __shared__ float As[TK][132];
    __shared__ float Bs[TK][132];

    const int tid = threadIdx.x;
    const int tx  = tid & 15;
    const int ty  = tid >> 4;
    const int lrow = tid >> 3;        // 0..31
    const int lk   = (tid & 7) * 4;   // 0,4,...,28

    u64 acc[8][4];
#pragma unroll
    for (int i = 0; i < 8; i++)
#pragma unroll
        for (int j = 0; j < 4; j++) acc[i][j] = 0ull;

#pragma unroll 1
    for (int kb = 0; kb < KCHUNK; kb += TK) {
        const int kg = k0 + kb + lk;
#pragma unroll
        for (int p = 0; p < 4; p++) {
            int row = p * 32 + lrow;
            float4 va = *(const float4*)(X + (size_t)(r0 + row) * NSEG + kg);
            float4 vb = *(const float4*)(X + (size_t)(c0 + row) * NSEG + kg);
            As[lk + 0][row] = va.x; As[lk + 1][row] = va.y;
            As[lk + 2][row] = va.z; As[lk + 3][row] = va.w;
            Bs[lk + 0][row] = vb.x; Bs[lk + 1][row] = vb.y;
            Bs[lk + 2][row] = vb.z; Bs[lk + 3][row] = vb.w;
        }
        __syncthreads();
#pragma unroll
        for (int kk = 0; kk < TK; kk++) {
            float4 a0 = *(const float4*)&As[kk][ty * 8];
            float4 a1 = *(const float4*)&As[kk][ty * 8 + 4];
            u64 b2[4];
#pragma unroll
            for (int jp = 0; jp < 4; jp++)
                b2[jp] = *(const u64*)&Bs[kk][tx * 8 + jp * 2];
            float av[8] = {a0.x, a0.y, a0.z, a0.w, a1.x, a1.y, a1.z, a1.w};
#pragma unroll
            for (int i = 0; i < 8; i++) {
                u64 ad = dup_f32(av[i]);
#pragma unroll
                for (int jp = 0; jp < 4; jp++) fma_x2(acc[i][jp], ad, b2[jp]);
            }
        }
        __syncthreads();
    }

    float* P = g_partial + (size_t)(split * NB + b) * CDIM * CDIM;
#pragma unroll
    for (int i = 0; i < 8; i++) {
        int r = r0 + ty * 8 + i;
#pragma unroll
        for (int jp = 0; jp < 4; jp++)
            *(u64*)(P + (size_t)r * CDIM + c0 + tx * 8 + jp * 2) = acc[i][jp];
    }
}

// ---------------------------------------------------------------------------
// Kernel 2: reduce split-k partials, row softmax of (-E), fold gamma.
// softmax(max(E)-E) == exp(min(E)-E)/sum  (shift-invariant, stable)
// grid NB*CDIM rows, 256 threads (one per column).
// ---------------------------------------------------------------------------
__global__ void softmax_kernel(const float* __restrict__ gamma) {
    const int row = blockIdx.x;   // b*256 + r
    const int d   = threadIdx.x;

    float e = 0.f;
#pragma unroll
    for (int s = 0; s < SPLITK; s++)
        e += g_partial[(size_t)s * NB * CDIM * CDIM + (size_t)row * CDIM + d];

    __shared__ float red[CDIM];
    red[d] = e;
    __syncthreads();
    for (int s = 128; s > 0; s >>= 1) {
        if (d < s) red[d] = fminf(red[d], red[d + s]);
        __syncthreads();
    }
    float minv = red[0];
    __syncthreads();

    float v = expf(minv - e);   // <= 1, no overflow
    red[d] = v;
    __syncthreads();
    for (int s = 128; s > 0; s >>= 1) {
        if (d < s) red[d] += red[d + s];
        __syncthreads();
    }
    float sum = red[0];

    g_attn[(size_t)row * CDIM + d] = gamma[0] * v / sum;
}

// ---------------------------------------------------------------------------
// Kernel 3: Y = attn' * X + X   (attn' already scaled by gamma)
// 128(c) x 128(j) block tile, k=256, 8x8 per thread (f32x2).
// grid (NSEG/128, 2, NB), 256 threads.
// ---------------------------------------------------------------------------
__global__ void __launch_bounds__(256, 2) out_kernel(const float* __restrict__ feats,
                                                     float* __restrict__ out) {
    const int b  = blockIdx.z;
    const int c0 = blockIdx.y * 128;
    const int j0 = blockIdx.x * 128;
    const float* X = feats + (size_t)b * CDIM * NSEG;
    const float* A = g_attn + (size_t)b * CDIM * CDIM;
    float* Y = out + (size_t)b * CDIM * NSEG;

    __shared__ float As2[TK][132];
    __shared__ float Xs[TK][128];

    const int tid = threadIdx.x;
    const int tx  = tid & 15;
    const int ty  = tid >> 4;
    const int lrow = tid >> 3;        // A-tile loading
    const int lk4  = (tid & 7) * 4;
    const int xk   = tid >> 5;        // X-tile loading
    const int xj   = (tid & 31) * 4;

    u64 acc[8][4];
#pragma unroll
    for (int i = 0; i < 8; i++)
#pragma unroll
        for (int j = 0; j < 4; j++) acc[i][j] = 0ull;

#pragma unroll 1
    for (int kb = 0; kb < CDIM; kb += TK) {
#pragma unroll
        for (int p = 0; p < 4; p++) {
            int c = p * 32 + lrow;
            float4 va = *(const float4*)(A + (size_t)(c0 + c) * CDIM + kb + lk4);
            As2[lk4 + 0][c] = va.x; As2[lk4 + 1][c] = va.y;
            As2[lk4 + 2][c] = va.z; As2[lk4 + 3][c] = va.w;
            int kr = p * 8 + xk;
            float4 vx = *(const float4*)(X + (size_t)(kb + kr) * NSEG + j0 + xj);
            *(float4*)&Xs[kr][xj] = vx;
        }
        __syncthreads();
#pragma unroll
        for (int kk = 0; kk < TK; kk++) {
            float4 a0 = *(const float4*)&As2[kk][ty * 8];
            float4 a1 = *(const float4*)&As2[kk][ty * 8 + 4];
            u64 b2[4];
#pragma unroll
            for (int jp = 0; jp < 4; jp++)
                b2[jp] = *(const u64*)&Xs[kk][tx * 8 + jp * 2];
            float av[8] = {a0.x, a0.y, a0.z, a0.w, a1.x, a1.y, a1.z, a1.w};
#pragma unroll
            for (int i = 0; i < 8; i++) {
                u64 ad = dup_f32(av[i]);
#pragma unroll
                for (int jp = 0; jp < 4; jp++) fma_x2(acc[i][jp], ad, b2[jp]);
            }
        }
        __syncthreads();
    }

    // epilogue: add residual X and store
#pragma unroll
    for (int i = 0; i < 8; i++) {
        int c = c0 + ty * 8 + i;
        const float* xr = X + (size_t)c * NSEG + j0 + tx * 8;
        float*       yr = Y + (size_t)c * NSEG + j0 + tx * 8;
#pragma unroll
        for (int jp = 0; jp < 4; jp++) {
            float2 v  = unpk(acc[i][jp]);
            float2 xv = *(const float2*)(xr + jp * 2);
            float2 o; o.x = v.x + xv.x; o.y = v.y + xv.y;
            *(float2*)(yr + jp * 2) = o;
        }
    }
}

// ---------------------------------------------------------------------------
extern "C" void kernel_launch(void* const* d_in, const int* in_sizes, int n_in,
                              void* d_out, int out_size) {
    const float* feats = (const float*)d_in[0];
    const float* gamma = (const float*)d_in[1];
    float* out = (float*)d_out;

    gram_kernel<<<dim3(4, SPLITK, NB), 256>>>(feats);
    softmax_kernel<<<NB * CDIM, CDIM>>>(gamma);
    out_kernel<<<dim3(NSEG / 128, CDIM / 128, NB), 256>>>(feats, out);
}

// round 3
// speedup vs baseline: 1.0013x; 1.0005x over previous
#include <cuda_runtime.h>
#include <cuda_bf16.h>

#define CDIM 256
#define NSEG 65536
#define NB 8
#define SPLITK 8
#define KCHUNK (NSEG / SPLITK)
#define TK 32

// scratch (allocation-free rule: __device__ globals)
__device__ float g_partial[SPLITK * NB * CDIM * CDIM]; // 16 MB
__device__ float g_attn[NB * CDIM * CDIM];             // 2 MB

typedef unsigned long long u64;

__device__ __forceinline__ u64 dup_f32(float x) {
    u64 r; asm("mov.b64 %0, {%1, %1};" : "=l"(r) : "f"(x)); return r;
}
__device__ __forceinline__ void fma_x2(u64 &d, u64 a, u64 b) {
    asm("fma.rn.f32x2 %0, %1, %2, %0;" : "+l"(d) : "l"(a), "l"(b));
}
__device__ __forceinline__ float2 unpk(u64 v) {
    float2 f; asm("mov.b64 {%0, %1}, %2;" : "=f"(f.x), "=f"(f.y) : "l"(v)); return f;
}

// ---------------------------------------------------------------------------
// Kernel 1: Gram partials. E_partial[s][b] = X[:, s-chunk] * X[:, s-chunk]^T
// 128x128 block tile, 8x8 per thread (f32x2-packed), TK=32.
// grid (4 tiles, SPLITK, NB), 256 threads.
// ---------------------------------------------------------------------------
__global__ void __launch_bounds__(256, 2) gram_kernel(const float* __restrict__ feats) {
    const int tile  = blockIdx.x;
    const int split = blockIdx.y;
    const int b     = blockIdx.z;
    const float* X  = feats + (size_t)b * CDIM * NSEG;
    const int r0 = (tile >> 1) * 128;
    const int c0 = (tile & 1) * 128;
    const int k0 = split * KCHUNK;

    __shared__ float As[TK][132];
    __shared__ float Bs[TK][132];

    const int tid = threadIdx.x;
    const int tx  = tid & 15;
    const int ty  = tid >> 4;
    const int lrow = tid >> 3;        // 0..31
    const int lk   = (tid & 7) * 4;   // 0,4,...,28

    u64 acc[8][4];
#pragma unroll
    for (int i = 0; i < 8; i++)
#pragma unroll
        for (int j = 0; j < 4; j++) acc[i][j] = 0ull;

#pragma unroll 1
    for (int kb = 0; kb < KCHUNK; kb += TK) {
        const int kg = k0 + kb + lk;
#pragma unroll
        for (int p = 0; p < 4; p++) {
            int row = p * 32 + lrow;
            float4 va = *(const float4*)(X + (size_t)(r0 + row) * NSEG + kg);
            float4 vb = *(const float4*)(X + (size_t)(c0 + row) * NSEG + kg);
            As[lk + 0][row] = va.x; As[lk + 1][row] = va.y;
            As[lk + 2][row] = va.z; As[lk + 3][row] = va.w;
            Bs[lk + 0][row] = vb.x; Bs[lk + 1][row] = vb.y;
            Bs[lk + 2][row] = vb.z; Bs[lk + 3][row] = vb.w;
        }
        __syncthreads();
#pragma unroll
        for (int kk = 0; kk < TK; kk++) {
            float4 a0 = *(const float4*)&As[kk][ty * 8];
            float4 a1 = *(const float4*)&As[kk][ty * 8 + 4];
            u64 b2[4];
#pragma unroll
            for (int jp = 0; jp < 4; jp++)
                b2[jp] = *(const u64*)&Bs[kk][tx * 8 + jp * 2];
            float av[8] = {a0.x, a0.y, a0.z, a0.w, a1.x, a1.y, a1.z, a1.w};
#pragma unroll
            for (int i = 0; i < 8; i++) {
                u64 ad = dup_f32(av[i]);
#pragma unroll
                for (int jp = 0; jp < 4; jp++) fma_x2(acc[i][jp], ad, b2[jp]);
            }
        }
        __syncthreads();
    }

    float* P = g_partial + (size_t)(split * NB + b) * CDIM * CDIM;
#pragma unroll
    for (int i = 0; i < 8; i++) {
        int r = r0 + ty * 8 + i;
#pragma unroll
        for (int jp = 0; jp < 4; jp++)
            *(u64*)(P + (size_t)r * CDIM + c0 + tx * 8 + jp * 2) = acc[i][jp];
    }
}

// ---------------------------------------------------------------------------
// Kernel 2: reduce split-k partials, row softmax of (-E), fold gamma.
// softmax(max(E)-E) == exp(min(E)-E)/sum  (shift-invariant, stable)
// grid NB*CDIM rows, 256 threads (one per column).
// ---------------------------------------------------------------------------
__global__ void softmax_kernel(const float* __restrict__ gamma) {
    const int row = blockIdx.x;   // b*256 + r
    const int d   = threadIdx.x;

    float e = 0.f;
#pragma unroll
    for (int s = 0; s < SPLITK; s++)
        e += g_partial[(size_t)s * NB * CDIM * CDIM + (size_t)row * CDIM + d];

    __shared__ float red[CDIM];
    red[d] = e;
    __syncthreads();
    for (int s = 128; s > 0; s >>= 1) {
        if (d < s) red[d] = fminf(red[d], red[d + s]);
        __syncthreads();
    }
    float minv = red[0];
    __syncthreads();

    float v = expf(minv - e);   // <= 1, no overflow
    red[d] = v;
    __syncthreads();
    for (int s = 128; s > 0; s >>= 1) {
        if (d < s) red[d] += red[d + s];
        __syncthreads();
    }
    float sum = red[0];

    g_attn[(size_t)row * CDIM + d] = gamma[0] * v / sum;
}

// ---------------------------------------------------------------------------
// Kernel 3: Y = attn' * X + X   (attn' already scaled by gamma)
// 128(c) x 128(j) block tile, k=256, 8x8 per thread (f32x2).
// grid (NSEG/128, 2, NB), 256 threads.
// ---------------------------------------------------------------------------
__global__ void __launch_bounds__(256, 2) out_kernel(const float* __restrict__ feats,
                                                     float* __restrict__ out) {
    const int b  = blockIdx.z;
    const int c0 = blockIdx.y * 128;
    const int j0 = blockIdx.x * 128;
    const float* X = feats + (size_t)b * CDIM * NSEG;
    const float* A = g_attn + (size_t)b * CDIM * CDIM;
    float* Y = out + (size_t)b * CDIM * NSEG;

    __shared__ float As2[TK][132];
    __shared__ float Xs[TK][128];

    const int tid = threadIdx.x;
    const int tx  = tid & 15;
    const int ty  = tid >> 4;
    const int lrow = tid >> 3;        // A-tile loading
    const int lk4  = (tid & 7) * 4;
    const int xk   = tid >> 5;        // X-tile loading
    const int xj   = (tid & 31) * 4;

    u64 acc[8][4];
#pragma unroll
    for (int i = 0; i < 8; i++)
#pragma unroll
        for (int j = 0; j < 4; j++) acc[i][j] = 0ull;

#pragma unroll 1
    for (int kb = 0; kb < CDIM; kb += TK) {
#pragma unroll
        for (int p = 0; p < 4; p++) {
            int c = p * 32 + lrow;
            float4 va = *(const float4*)(A + (size_t)(c0 + c) * CDIM + kb + lk4);
            As2[lk4 + 0][c] = va.x; As2[lk4 + 1][c] = va.y;
            As2[lk4 + 2][c] = va.z; As2[lk4 + 3][c] = va.w;
            int kr = p * 8 + xk;
            float4 vx = *(const float4*)(X + (size_t)(kb + kr) * NSEG + j0 + xj);
            *(float4*)&Xs[kr][xj] = vx;
        }
        __syncthreads();
#pragma unroll
        for (int kk = 0; kk < TK; kk++) {
            float4 a0 = *(const float4*)&As2[kk][ty * 8];
            float4 a1 = *(const float4*)&As2[kk][ty * 8 + 4];
            u64 b2[4];
#pragma unroll
            for (int jp = 0; jp < 4; jp++)
                b2[jp] = *(const u64*)&Xs[kk][tx * 8 + jp * 2];
            float av[8] = {a0.x, a0.y, a0.z, a0.w, a1.x, a1.y, a1.z, a1.w};
#pragma unroll
            for (int i = 0; i < 8; i++) {
                u64 ad = dup_f32(av[i]);
#pragma unroll
                for (int jp = 0; jp < 4; jp++) fma_x2(acc[i][jp], ad, b2[jp]);
            }
        }
        __syncthreads();
    }

    // epilogue: add residual X and store
#pragma unroll
    for (int i = 0; i < 8; i++) {
        int c = c0 + ty * 8 + i;
        const float* xr = X + (size_t)c * NSEG + j0 + tx * 8;
        float*       yr = Y + (size_t)c * NSEG + j0 + tx * 8;
#pragma unroll
        for (int jp = 0; jp < 4; jp++) {
            float2 v  = unpk(acc[i][jp]);
            float2 xv = *(const float2*)(xr + jp * 2);
            float2 o; o.x = v.x + xv.x; o.y = v.y + xv.y;
            *(float2*)(yr + jp * 2) = o;
        }
    }
}

// ---------------------------------------------------------------------------
extern "C" void kernel_launch(void* const* d_in, const int* in_sizes, int n_in,
                              void* d_out, int out_size) {
    const float* feats = (const float*)d_in[0];
    const float* gamma = (const float*)d_in[1];
    float* out = (float*)d_out;

    gram_kernel<<<dim3(4, SPLITK, NB), 256>>>(feats);
    softmax_kernel<<<NB * CDIM, CDIM>>>(gamma);
    out_kernel<<<dim3(NSEG / 128, CDIM / 128, NB), 256>>>(feats, out);
}

// round 6
// speedup vs baseline: 4.9685x; 4.9621x over previous
#include <cuda_runtime.h>
#include <cuda_bf16.h>
#include <cstdint>

#define CDIM 256
#define NSEG 65536
#define NB 8
#define GSPLIT 16
#define KCHUNK (NSEG / GSPLIT)            // 4096
#define GCH 64
#define GNCH (KCHUNK / GCH)               // 64 chunks per gram CTA
#define GRAM_SMEM (1024 + 3 * 32768)
#define TK 32

#if defined(__CUDA_ARCH_FEAT_SM103_ALL) || defined(__CUDA_ARCH_FEAT_SM100_ALL)
#define HAS_TC 1
#else
#define HAS_TC 0
#endif

__device__ float g_partial[(size_t)GSPLIT * NB * CDIM * CDIM]; // 32 MB
__device__ int   g_cnt[NB * CDIM];
__device__ int   g_sp_idx[NB * CDIM * CDIM];
__device__ float g_sp_val[NB * CDIM * CDIM];

typedef unsigned long long u64;

__device__ __forceinline__ u64 dup_f32(float x) {
    u64 r; asm("mov.b64 %0, {%1, %1};" : "=l"(r) : "f"(x)); return r;
}
__device__ __forceinline__ void fma_x2(u64 &d, u64 a, u64 b) {
    asm("fma.rn.f32x2 %0, %1, %2, %0;" : "+l"(d) : "l"(a), "l"(b));
}

// ---------------------------------------------------------------------------
// tcgen05 gram (compiled only in arch-specific passes)
// ---------------------------------------------------------------------------
__global__ void __launch_bounds__(256, 1) gram_tc(const float* __restrict__ feats) {
#if HAS_TC
    extern __shared__ __align__(1024) char smem[];
    uint32_t sb;
    asm("{ .reg .u64 t; cvta.to.shared.u64 t, %1; cvt.u32.u64 %0, t; }" : "=r"(sb) : "l"(smem));
    const int tid = threadIdx.x, wid = tid >> 5;
    const float* X = feats + (size_t)blockIdx.y * CDIM * NSEG;
    const int k0 = blockIdx.x * KCHUNK;

    if (wid == 0)
        asm volatile("tcgen05.alloc.cta_group::1.sync.aligned.shared::cta.b32 [%0], %1;"
                     :: "r"(sb), "r"(512u) : "memory");
    if (tid == 0)
        asm volatile("mbarrier.init.shared.b64 [%0], %1;" :: "r"(sb + 8), "r"(1u) : "memory");
    __syncthreads();
    uint32_t tmem;
    asm volatile("ld.shared.b32 %0, [%1];" : "=r"(tmem) : "r"(sb));

    const uint32_t H = sb + 1024, M = H + 32768, L = M + 32768;
    // K-major SW128 descriptor base: layout=2, version=1, SBO=64, LBO=1
    const uint64_t DBASE = 0x4000404000010000ull;
    // F32 acc, BF16 a/b, N=256, M=128
    const uint32_t IDESC = (1u << 4) | (1u << 7) | (1u << 10) | ((CDIM / 8) << 17) | (8u << 24);

    float4 rg[16];
#pragma unroll
    for (int p = 0; p < 16; p++) {
        int g = p * 256 + tid;
        rg[p] = *(const float4*)(X + (size_t)(g >> 4) * NSEG + k0 + (g & 15) * 4);
    }

    for (int i = 0; i < GNCH; i++) {
        if (i) { // wait commit (i-1): parity (i-1)&1
            uint32_t par = (i - 1) & 1, done;
            asm volatile("{\n\t.reg .pred p;\n\t"
                "mbarrier.try_wait.parity.acquire.cta.shared::cta.b64 p, [%1], %2;\n\t"
                "selp.b32 %0, 1, 0, p;\n\t}" : "=r"(done) : "r"(sb + 8), "r"(par) : "memory");
            if (!done)
                asm volatile("{\n\t.reg .pred P1;\n\t"
                    "WL_%=:\n\t"
                    "mbarrier.try_wait.parity.acquire.cta.shared::cta.b64 P1, [%0], %1, 0x989680;\n\t"
                    "@P1 bra.uni WD_%=;\n\tbra.uni WL_%=;\n\tWD_%=:\n\t}"
                    :: "r"(sb + 8), "r"(par) : "memory");
        }
#pragma unroll
        for (int p = 0; p < 16; p++) {
            int g = p * 256 + tid;
            float4 v = rg[p];
            __nv_bfloat162 h0 = __floats2bfloat162_rn(v.x, v.y);
            __nv_bfloat162 h1 = __floats2bfloat162_rn(v.z, v.w);
            float2 hf0 = __bfloat1622float2(h0), hf1 = __bfloat1622float2(h1);
            float r0x = v.x - hf0.x, r0y = v.y - hf0.y;
            float r1x = v.z - hf1.x, r1y = v.w - hf1.y;
            __nv_bfloat162 m0 = __floats2bfloat162_rn(r0x, r0y);
            __nv_bfloat162 m1 = __floats2bfloat162_rn(r1x, r1y);
            float2 mf0 = __bfloat1622float2(m0), mf1 = __bfloat1622float2(m1);
            __nv_bfloat162 l0 = __floats2bfloat162_rn(r0x - mf0.x, r0y - mf0.y);
            __nv_bfloat162 l1 = __floats2bfloat162_rn(r1x - mf1.x, r1y - mf1.y);
            uint32_t off = (uint32_t)((g >> 4) * 128 + (g & 15) * 8);
            off ^= (off >> 3) & 0x70;
            asm volatile("st.shared.v2.b32 [%0], {%1,%2};" :: "r"(H + off),
                         "r"(*(uint32_t*)&h0), "r"(*(uint32_t*)&h1) : "memory");
            asm volatile("st.shared.v2.b32 [%0], {%1,%2};" :: "r"(M + off),
                         "r"(*(uint32_t*)&m0), "r"(*(uint32_t*)&m1) : "memory");
            asm volatile("st.shared.v2.b32 [%0], {%1,%2};" :: "r"(L + off),
                         "r"(*(uint32_t*)&l0), "r"(*(uint32_t*)&l1) : "memory");
        }
        asm volatile("fence.proxy.async.shared::cta;" ::: "memory");
        __syncthreads();

        if (wid == 0) {
            uint32_t is_e;
            asm volatile("{\n\t.reg .pred p;\n\telect.sync _|p, 0xFFFFFFFF;\n\t"
                         "selp.b32 %0, 1, 0, p;\n\t}" : "=r"(is_e));
            if (is_e) {
                uint64_t dh = DBASE | ((H >> 4) & 0x3FFF);
                uint64_t dm = DBASE | ((M >> 4) & 0x3FFF);
                uint64_t dl = DBASE | ((L >> 4) & 0x3FFF);
#pragma unroll
                for (int ks = 0; ks < 4; ks++) {
                    uint64_t oh = dh + 2 * ks, om = dm + 2 * ks, ol = dl + 2 * ks;
                    bool f = (i == 0 && ks == 0);
#pragma unroll
                    for (int hf = 0; hf < 2; hf++) { // A rows +128 -> desc +1024 units
                        uint32_t d = tmem + hf * 256;
                        uint64_t ah = oh + hf * 1024, am = om + hf * 1024, al = ol + hf * 1024;
                        uint64_t av[6] = {ah, ah, am, ah, al, am};
                        uint64_t bv[6] = {oh, om, oh, ol, oh, om};
#pragma unroll
                        for (int t = 0; t < 6; t++) {
                            uint32_t en = (f && t == 0) ? 0u : 1u;
                            asm volatile("{\n\t.reg .pred p;\n\tsetp.ne.u32 p, %4, 0;\n\t"
                                "tcgen05.mma.cta_group::1.kind::f16 [%0], %1, %2, %3, {%5,%5,%5,%5}, p;\n\t}"
                                :: "r"(d), "l"(av[t]), "l"(bv[t]), "r"(IDESC), "r"(en), "r"(0u)
                                : "memory");
                        }
                    }
                }
                asm volatile("tcgen05.commit.cta_group::1.mbarrier::arrive::one.shared::cluster.b64 [%0];"
                             :: "r"(sb + 8) : "memory");
            }
        }
        if (i + 1 < GNCH) {
            const int kc = k0 + (i + 1) * GCH;
#pragma unroll
            for (int p = 0; p < 16; p++) {
                int g = p * 256 + tid;
                rg[p] = *(const float4*)(X + (size_t)(g >> 4) * NSEG + kc + (g & 15) * 4);
            }
        }
    }
    { // drain final commit
        uint32_t par = (GNCH - 1) & 1, done;
        asm volatile("{\n\t.reg .pred p;\n\t"
            "mbarrier.try_wait.parity.acquire.cta.shared::cta.b64 p, [%1], %2;\n\t"
            "selp.b32 %0, 1, 0, p;\n\t}" : "=r"(done) : "r"(sb + 8), "r"(par) : "memory");
        if (!done)
            asm volatile("{\n\t.reg .pred P1;\n\t"
                "WL2_%=:\n\t"
                "mbarrier.try_wait.parity.acquire.cta.shared::cta.b64 P1, [%0], %1, 0x989680;\n\t"
                "@P1 bra.uni WD2_%=;\n\tbra.uni WL2_%=;\n\tWD2_%=:\n\t}"
                :: "r"(sb + 8), "r"(par) : "memory");
    }
    asm volatile("tcgen05.fence::after_thread_sync;" ::: "memory");

    float* P = g_partial + ((size_t)blockIdx.x * NB + blockIdx.y) * (CDIM * CDIM);
    const int row = (wid >> 2) * 128 + (wid & 3) * 32 + (tid & 31);
    const uint32_t db = tmem + (wid >> 2) * 256;
#pragma unroll 1
    for (int cg = 0; cg < 8; cg++) {
        uint32_t r[32];
        asm volatile("tcgen05.ld.sync.aligned.32x32b.x32.b32 "
            "{%0,%1,%2,%3,%4,%5,%6,%7,%8,%9,%10,%11,%12,%13,%14,%15,"
            "%16,%17,%18,%19,%20,%21,%22,%23,%24,%25,%26,%27,%28,%29,%30,%31}, [%32];"
            : "=r"(r[0]),"=r"(r[1]),"=r"(r[2]),"=r"(r[3]),"=r"(r[4]),"=r"(r[5]),
              "=r"(r[6]),"=r"(r[7]),"=r"(r[8]),"=r"(r[9]),"=r"(r[10]),"=r"(r[11]),
              "=r"(r[12]),"=r"(r[13]),"=r"(r[14]),"=r"(r[15]),"=r"(r[16]),"=r"(r[17]),
              "=r"(r[18]),"=r"(r[19]),"=r"(r[20]),"=r"(r[21]),"=r"(r[22]),"=r"(r[23]),
              "=r"(r[24]),"=r"(r[25]),"=r"(r[26]),"=r"(r[27]),"=r"(r[28]),"=r"(r[29]),
              "=r"(r[30]),"=r"(r[31]) : "r"(db + cg * 32));
        asm volatile("tcgen05.wait::ld.sync.aligned;" ::: "memory");
        uint4* dst = (uint4*)(P + (size_t)row * CDIM + cg * 32);
#pragma unroll
        for (int q = 0; q < 8; q++)
            dst[q] = make_uint4(r[q * 4], r[q * 4 + 1], r[q * 4 + 2], r[q * 4 + 3]);
    }
    __syncthreads();
    if (wid == 0)
        asm volatile("tcgen05.dealloc.cta_group::1.sync.aligned.b32 %0, %1;"
                     :: "r"(tmem), "r"(512u));
#endif
}

// ---------------------------------------------------------------------------
// SIMT fallback gram (no-op when tcgen05 path is live).
// grid (4 tiles, GSPLIT, NB), 256 threads. R1-validated numerics.
// ---------------------------------------------------------------------------
__global__ void __launch_bounds__(256, 2) gram_simt(const float* __restrict__ feats) {
#if !HAS_TC
    const int tile = blockIdx.x, split = blockIdx.y, b = blockIdx.z;
    const float* X = feats + (size_t)b * CDIM * NSEG;
    const int r0 = (tile >> 1) * 128, c0 = (tile & 1) * 128;
    const int k0 = split * KCHUNK;

    __shared__ float As[TK][132];
    __shared__ float Bs[TK][132];

    const int tid = threadIdx.x;
    const int tx = tid & 15, ty = tid >> 4;
    const int lrow = tid >> 3, lk = (tid & 7) * 4;

    u64 acc[8][4];
#pragma unroll
    for (int i = 0; i < 8; i++)
#pragma unroll
        for (int j = 0; j < 4; j++) acc[i][j] = 0ull;

#pragma unroll 1
    for (int kb = 0; kb < KCHUNK; kb += TK) {
        const int kg = k0 + kb + lk;
#pragma unroll
        for (int p = 0; p < 4; p++) {
            int row = p * 32 + lrow;
            float4 va = *(const float4*)(X + (size_t)(r0 + row) * NSEG + kg);
            float4 vb = *(const float4*)(X + (size_t)(c0 + row) * NSEG + kg);
            As[lk + 0][row] = va.x; As[lk + 1][row] = va.y;
            As[lk + 2][row] = va.z; As[lk + 3][row] = va.w;
            Bs[lk + 0][row] = vb.x; Bs[lk + 1][row] = vb.y;
            Bs[lk + 2][row] = vb.z; Bs[lk + 3][row] = vb.w;
        }
        __syncthreads();
#pragma unroll
        for (int kk = 0; kk < TK; kk++) {
            float4 a0 = *(const float4*)&As[kk][ty * 8];
            float4 a1 = *(const float4*)&As[kk][ty * 8 + 4];
            u64 b2[4];
#pragma unroll
            for (int jp = 0; jp < 4; jp++)
                b2[jp] = *(const u64*)&Bs[kk][tx * 8 + jp * 2];
            float av[8] = {a0.x, a0.y, a0.z, a0.w, a1.x, a1.y, a1.z, a1.w};
#pragma unroll
            for (int i = 0; i < 8; i++) {
                u64 ad = dup_f32(av[i]);
#pragma unroll
                for (int jp = 0; jp < 4; jp++) fma_x2(acc[i][jp], ad, b2[jp]);
            }
        }
        __syncthreads();
    }
    float* P = g_partial + ((size_t)split * NB + b) * (CDIM * CDIM);
#pragma unroll
    for (int i = 0; i < 8; i++) {
        int r = r0 + ty * 8 + i;
#pragma unroll
        for (int jp = 0; jp < 4; jp++)
            *(u64*)(P + (size_t)r * CDIM + c0 + tx * 8 + jp * 2) = acc[i][jp];
    }
#endif
}

// ---------------------------------------------------------------------------
// Softmax + exact-sparsity extraction. attn[c,d] = gamma*exp(minE-E)/S.
// Keeps entries with (E - minE) < 100 (dropped terms < 1e-43).
// ---------------------------------------------------------------------------
__global__ void softmax_kernel(const float* __restrict__ gamma) {
    const int row = blockIdx.x;
    const int d = threadIdx.x;
    float e = 0.f;
#pragma unroll
    for (int s = 0; s < GSPLIT; s++)
        e += g_partial[(size_t)s * (NB * CDIM * CDIM) + (size_t)row * CDIM + d];

    __shared__ float red[CDIM];
    __shared__ int wb[9];
    red[d] = e;
    __syncthreads();
    for (int s = 128; s > 0; s >>= 1) {
        if (d < s) red[d] = fminf(red[d], red[d + s]);
        __syncthreads();
    }
    float minv = red[0];
    __syncthreads();
    float v = expf(minv - e);
    red[d] = v;
    __syncthreads();
    for (int s = 128; s > 0; s >>= 1) {
        if (d < s) red[d] += red[d + s];
        __syncthreads();
    }
    float S = red[0];

    bool keep = (e - minv) < 100.0f;
    unsigned msk = __ballot_sync(0xffffffffu, keep);
    int lane = d & 31, w = d >> 5;
    if (lane == 0) wb[w] = __popc(msk);
    __syncthreads();
    if (d == 0) {
        int acc = 0;
        for (int t = 0; t < 8; t++) { int x = wb[t]; wb[t] = acc; acc += x; }
        wb[8] = acc;
    }
    __syncthreads();
    if (keep) {
        int pos = wb[w] + __popc(msk & ((1u << lane) - 1));
        g_sp_idx[row * CDIM + pos] = d;
        g_sp_val[row * CDIM + pos] = gamma[0] * v / S;
    }
    if (d == 0) g_cnt[row] = wb[8];
}

// ---------------------------------------------------------------------------
// Sparse out: y[c,j] = sum_k val[c,k] * x[d_k, j] + x[c,j]
// ---------------------------------------------------------------------------
__global__ void __launch_bounds__(256) out_sparse(const float* __restrict__ feats,
                                                  float* __restrict__ out) {
    const int c = blockIdx.x, b = blockIdx.z;
    const int row = b * CDIM + c;
    const float* Xb = feats + (size_t)b * CDIM * NSEG;
    const int j0 = blockIdx.y * 4096 + threadIdx.x * 4;

    float4 acc[4];
#pragma unroll
    for (int q = 0; q < 4; q++)
        acc[q] = *(const float4*)(Xb + (size_t)c * NSEG + j0 + q * 1024);

    const int cnt = g_cnt[row];
    for (int k = 0; k < cnt; k++) {
        const int dd = g_sp_idx[row * CDIM + k];
        const float v = g_sp_val[row * CDIM + k];
        const float* xp = Xb + (size_t)dd * NSEG + j0;
#pragma unroll
        for (int q = 0; q < 4; q++) {
            float4 x4 = *(const float4*)(xp + q * 1024);
            acc[q].x = fmaf(v, x4.x, acc[q].x);
            acc[q].y = fmaf(v, x4.y, acc[q].y);
            acc[q].z = fmaf(v, x4.z, acc[q].z);
            acc[q].w = fmaf(v, x4.w, acc[q].w);
        }
    }
    float* yp = out + (size_t)b * CDIM * NSEG + (size_t)c * NSEG + j0;
#pragma unroll
    for (int q = 0; q < 4; q++)
        *(float4*)(yp + q * 1024) = acc[q];
}

// ---------------------------------------------------------------------------
extern "C" void kernel_launch(void* const* d_in, const int* in_sizes, int n_in,
                              void* d_out, int out_size) {
    const float* feats = (const float*)d_in[0];
    const float* gamma = (const float*)d_in[1];
    float* out = (float*)d_out;

    static bool attr_set = false;
    if (!attr_set) {
        cudaFuncSetAttribute(gram_tc, cudaFuncAttributeMaxDynamicSharedMemorySize, GRAM_SMEM);
        attr_set = true;
    }
    gram_tc<<<dim3(GSPLIT, NB), 256, GRAM_SMEM>>>(feats);
    gram_simt<<<dim3(4, GSPLIT, NB), 256>>>(feats);
    softmax_kernel<<<NB * CDIM, CDIM>>>(gamma);
    out_sparse<<<dim3(CDIM, 16, NB), 256>>>(feats, out);
}

// round 7
// speedup vs baseline: 5.0587x; 1.0181x over previous
#include <cuda_runtime.h>
#include <cuda_bf16.h>
#include <cstdint>

#define CDIM 256
#define NSEG 65536
#define NB 8
#define GSPLIT 16
#define KCHUNK (NSEG / GSPLIT)            // 4096
#define GCH 64
#define GNCH (KCHUNK / GCH)               // 64 chunks per gram CTA
#define BUFB (3 * 32768)                  // one H/M/L buffer set: 96 KB
#define GRAM_SMEM (1024 + 2 * BUFB)       // 197,632 B (double-buffered)

#if defined(__CUDA_ARCH_FEAT_SM103_ALL) || defined(__CUDA_ARCH_FEAT_SM100_ALL)
#define HAS_TC 1
#else
#define HAS_TC 0
#endif

__device__ float g_partial[(size_t)GSPLIT * NB * CDIM * CDIM]; // 32 MB
__device__ int   g_cnt[NB * CDIM];
__device__ int   g_sp_idx[NB * CDIM * CDIM];
__device__ float g_sp_val[NB * CDIM * CDIM];

#if HAS_TC
#define MBAR_WAIT(m, par) do { \
    uint32_t _m = (uint32_t)(m), _p = (uint32_t)(par), _d; \
    asm volatile("{\n\t.reg .pred p;\n\t" \
        "mbarrier.try_wait.parity.acquire.cta.shared::cta.b64 p, [%1], %2;\n\t" \
        "selp.b32 %0, 1, 0, p;\n\t}" : "=r"(_d) : "r"(_m), "r"(_p) : "memory"); \
    if (!_d) { \
        asm volatile("{\n\t.reg .pred P1;\n\t" \
            "WL_%=:\n\t" \
            "mbarrier.try_wait.parity.acquire.cta.shared::cta.b64 P1, [%0], %1, 0x989680;\n\t" \
            "@P1 bra.uni WD_%=;\n\tbra.uni WL_%=;\n\tWD_%=:\n\t}" \
            :: "r"(_m), "r"(_p) : "memory"); \
    } } while (0)
#endif

// ---------------------------------------------------------------------------
// tcgen05 gram: per CTA the full 256x256 E-partial over a K=4096 span.
// 3-way bf16 split (6 terms), two M=128/N=256 TMEM accumulators (512 cols),
// DOUBLE-BUFFERED smem so convert(i+1)+LDG overlap MMA(i).
// ---------------------------------------------------------------------------
__global__ void __launch_bounds__(256, 1) gram_tc(const float* __restrict__ feats) {
#if HAS_TC
    extern __shared__ __align__(1024) char smem[];
    uint32_t sb;
    asm("{ .reg .u64 t; cvta.to.shared.u64 t, %1; cvt.u32.u64 %0, t; }" : "=r"(sb) : "l"(smem));
    const int tid = threadIdx.x, wid = tid >> 5;
    const float* X = feats + (size_t)blockIdx.y * CDIM * NSEG;
    const int k0 = blockIdx.x * KCHUNK;

    if (wid == 0)
        asm volatile("tcgen05.alloc.cta_group::1.sync.aligned.shared::cta.b32 [%0], %1;"
                     :: "r"(sb), "r"(512u) : "memory");
    if (tid == 0) {
        asm volatile("mbarrier.init.shared.b64 [%0], %1;" :: "r"(sb + 8), "r"(1u) : "memory");
        asm volatile("mbarrier.init.shared.b64 [%0], %1;" :: "r"(sb + 16), "r"(1u) : "memory");
    }
    __syncthreads();
    uint32_t tmem;
    asm volatile("ld.shared.b32 %0, [%1];" : "=r"(tmem) : "r"(sb));

    // K-major SW128 descriptor base: layout=2, version=1, SBO=64, LBO=1
    const uint64_t DBASE = 0x4000404000010000ull;
    // F32 acc, BF16 a/b, N=256, M=128
    const uint32_t IDESC = (1u << 4) | (1u << 7) | (1u << 10) | ((CDIM / 8) << 17) | (8u << 24);

    float4 rg[16];
#pragma unroll
    for (int p = 0; p < 16; p++) {
        int g = p * 256 + tid;
        rg[p] = *(const float4*)(X + (size_t)(g >> 4) * NSEG + k0 + (g & 15) * 4);
    }

    for (int i = 0; i < GNCH; i++) {
        const int s = i & 1;
        const uint32_t mb = sb + 8 + s * 8;
        // buffer s was last consumed by MMA(i-2): wait its commit before overwrite
        if (i >= 2) MBAR_WAIT(mb, ((i - 2) >> 1) & 1);

        const uint32_t H = sb + 1024 + s * BUFB, M = H + 32768, L = M + 32768;
#pragma unroll
        for (int p = 0; p < 16; p++) {
            int g = p * 256 + tid;
            float4 v = rg[p];
            __nv_bfloat162 h0 = __floats2bfloat162_rn(v.x, v.y);
            __nv_bfloat162 h1 = __floats2bfloat162_rn(v.z, v.w);
            float2 hf0 = __bfloat1622float2(h0), hf1 = __bfloat1622float2(h1);
            float r0x = v.x - hf0.x, r0y = v.y - hf0.y;
            float r1x = v.z - hf1.x, r1y = v.w - hf1.y;
            __nv_bfloat162 m0 = __floats2bfloat162_rn(r0x, r0y);
            __nv_bfloat162 m1 = __floats2bfloat162_rn(r1x, r1y);
            float2 mf0 = __bfloat1622float2(m0), mf1 = __bfloat1622float2(m1);
            __nv_bfloat162 l0 = __floats2bfloat162_rn(r0x - mf0.x, r0y - mf0.y);
            __nv_bfloat162 l1 = __floats2bfloat162_rn(r1x - mf1.x, r1y - mf1.y);
            uint32_t off = (uint32_t)((g >> 4) * 128 + (g & 15) * 8);
            off ^= (off >> 3) & 0x70;
            asm volatile("st.shared.v2.b32 [%0], {%1,%2};" :: "r"(H + off),
                         "r"(*(uint32_t*)&h0), "r"(*(uint32_t*)&h1) : "memory");
            asm volatile("st.shared.v2.b32 [%0], {%1,%2};" :: "r"(M + off),
                         "r"(*(uint32_t*)&m0), "r"(*(uint32_t*)&m1) : "memory");
            asm volatile("st.shared.v2.b32 [%0], {%1,%2};" :: "r"(L + off),
                         "r"(*(uint32_t*)&l0), "r"(*(uint32_t*)&l1) : "memory");
        }
        asm volatile("fence.proxy.async.shared::cta;" ::: "memory");
        __syncthreads();

        if (wid == 0) {
            uint32_t is_e;
            asm volatile("{\n\t.reg .pred p;\n\telect.sync _|p, 0xFFFFFFFF;\n\t"
                         "selp.b32 %0, 1, 0, p;\n\t}" : "=r"(is_e));
            if (is_e) {
                uint64_t dh = DBASE | ((H >> 4) & 0x3FFF);
                uint64_t dm = DBASE | ((M >> 4) & 0x3FFF);
                uint64_t dl = DBASE | ((L >> 4) & 0x3FFF);
#pragma unroll
                for (int ks = 0; ks < 4; ks++) {
                    uint64_t oh = dh + 2 * ks, om = dm + 2 * ks, ol = dl + 2 * ks;
                    bool f = (i == 0 && ks == 0);
#pragma unroll
                    for (int hf = 0; hf < 2; hf++) { // A rows +128 -> desc +1024 units
                        uint32_t d = tmem + hf * 256;
                        uint64_t ah = oh + hf * 1024, am = om + hf * 1024, al = ol + hf * 1024;
                        uint64_t av[6] = {ah, ah, am, ah, al, am};
                        uint64_t bv[6] = {oh, om, oh, ol, oh, om};
#pragma unroll
                        for (int t = 0; t < 6; t++) {
                            uint32_t en = (f && t == 0) ? 0u : 1u;
                            asm volatile("{\n\t.reg .pred p;\n\tsetp.ne.u32 p, %4, 0;\n\t"
                                "tcgen05.mma.cta_group::1.kind::f16 [%0], %1, %2, %3, {%5,%5,%5,%5}, p;\n\t}"
                                :: "r"(d), "l"(av[t]), "l"(bv[t]), "r"(IDESC), "r"(en), "r"(0u)
                                : "memory");
                        }
                    }
                }
                asm volatile("tcgen05.commit.cta_group::1.mbarrier::arrive::one.shared::cluster.b64 [%0];"
                             :: "r"(mb) : "memory");
            }
        }
        if (i + 1 < GNCH) { // overlap next chunk's loads with MMA(i)
            const int kc = k0 + (i + 1) * GCH;
#pragma unroll
            for (int p = 0; p < 16; p++) {
                int g = p * 256 + tid;
                rg[p] = *(const float4*)(X + (size_t)(g >> 4) * NSEG + kc + (g & 15) * 4);
            }
        }
    }
    // drain both buffers' final commits
    MBAR_WAIT(sb + 8 + ((GNCH - 2) & 1) * 8, ((GNCH - 2) >> 1) & 1);
    MBAR_WAIT(sb + 8 + ((GNCH - 1) & 1) * 8, ((GNCH - 1) >> 1) & 1);
    asm volatile("tcgen05.fence::after_thread_sync;" ::: "memory");

    float* P = g_partial + ((size_t)blockIdx.x * NB + blockIdx.y) * (CDIM * CDIM);
    const int row = (wid >> 2) * 128 + (wid & 3) * 32 + (tid & 31);
    const uint32_t db = tmem + (wid >> 2) * 256;
#pragma unroll 1
    for (int cg = 0; cg < 8; cg++) {
        uint32_t r[32];
        asm volatile("tcgen05.ld.sync.aligned.32x32b.x32.b32 "
            "{%0,%1,%2,%3,%4,%5,%6,%7,%8,%9,%10,%11,%12,%13,%14,%15,"
            "%16,%17,%18,%19,%20,%21,%22,%23,%24,%25,%26,%27,%28,%29,%30,%31}, [%32];"
            : "=r"(r[0]),"=r"(r[1]),"=r"(r[2]),"=r"(r[3]),"=r"(r[4]),"=r"(r[5]),
              "=r"(r[6]),"=r"(r[7]),"=r"(r[8]),"=r"(r[9]),"=r"(r[10]),"=r"(r[11]),
              "=r"(r[12]),"=r"(r[13]),"=r"(r[14]),"=r"(r[15]),"=r"(r[16]),"=r"(r[17]),
              "=r"(r[18]),"=r"(r[19]),"=r"(r[20]),"=r"(r[21]),"=r"(r[22]),"=r"(r[23]),
              "=r"(r[24]),"=r"(r[25]),"=r"(r[26]),"=r"(r[27]),"=r"(r[28]),"=r"(r[29]),
              "=r"(r[30]),"=r"(r[31]) : "r"(db + cg * 32));
        asm volatile("tcgen05.wait::ld.sync.aligned;" ::: "memory");
        uint4* dst = (uint4*)(P + (size_t)row * CDIM + cg * 32);
#pragma unroll
        for (int q = 0; q < 8; q++)
            dst[q] = make_uint4(r[q * 4], r[q * 4 + 1], r[q * 4 + 2], r[q * 4 + 3]);
    }
    __syncthreads();
    if (wid == 0)
        asm volatile("tcgen05.dealloc.cta_group::1.sync.aligned.b32 %0, %1;"
                     :: "r"(tmem), "r"(512u));
#endif
}

// ---------------------------------------------------------------------------
// Softmax + exact-sparsity extraction. attn[c,d] = gamma*exp(minE-E)/S.
// Keeps entries with (E - minE) < 100 (dropped terms < 1e-43).
// ---------------------------------------------------------------------------
__global__ void softmax_kernel(const float* __restrict__ gamma) {
    const int row = blockIdx.x;
    const int d = threadIdx.x;
    float e = 0.f;
#pragma unroll
    for (int s = 0; s < GSPLIT; s++)
        e += g_partial[(size_t)s * (NB * CDIM * CDIM) + (size_t)row * CDIM + d];

    __shared__ float red[CDIM];
    __shared__ int wb[9];
    red[d] = e;
    __syncthreads();
    for (int s = 128; s > 0; s >>= 1) {
        if (d < s) red[d] = fminf(red[d], red[d + s]);
        __syncthreads();
    }
    float minv = red[0];
    __syncthreads();
    float v = expf(minv - e);
    red[d] = v;
    __syncthreads();
    for (int s = 128; s > 0; s >>= 1) {
        if (d < s) red[d] += red[d + s];
        __syncthreads();
    }
    float S = red[0];

    bool keep = (e - minv) < 100.0f;
    unsigned msk = __ballot_sync(0xffffffffu, keep);
    int lane = d & 31, w = d >> 5;
    if (lane == 0) wb[w] = __popc(msk);
    __syncthreads();
    if (d == 0) {
        int acc = 0;
        for (int t = 0; t < 8; t++) { int x = wb[t]; wb[t] = acc; acc += x; }
        wb[8] = acc;
    }
    __syncthreads();
    if (keep) {
        int pos = wb[w] + __popc(msk & ((1u << lane) - 1));
        g_sp_idx[row * CDIM + pos] = d;
        g_sp_val[row * CDIM + pos] = gamma[0] * v / S;
    }
    if (d == 0) g_cnt[row] = wb[8];
}

// ---------------------------------------------------------------------------
// Sparse out: y[c,j] = sum_k val[c,k] * x[d_k, j] + x[c,j]
// Output stored evict-first (__stcs) so Y writes don't evict the L2-resident X.
// ---------------------------------------------------------------------------
__global__ void __launch_bounds__(256) out_sparse(const float* __restrict__ feats,
                                                  float* __restrict__ out) {
    const int c = blockIdx.x, b = blockIdx.z;
    const int row = b * CDIM + c;
    const float* Xb = feats + (size_t)b * CDIM * NSEG;
    const int j0 = blockIdx.y * 4096 + threadIdx.x * 4;

    float4 acc[4];
#pragma unroll
    for (int q = 0; q < 4; q++)
        acc[q] = *(const float4*)(Xb + (size_t)c * NSEG + j0 + q * 1024);

    const int cnt = g_cnt[row];
    for (int k = 0; k < cnt; k++) {
        const int dd = g_sp_idx[row * CDIM + k];
        const float v = g_sp_val[row * CDIM + k];
        const float* xp = Xb + (size_t)dd * NSEG + j0;
#pragma unroll
        for (int q = 0; q < 4; q++) {
            float4 x4 = *(const float4*)(xp + q * 1024);
            acc[q].x = fmaf(v, x4.x, acc[q].x);
            acc[q].y = fmaf(v, x4.y, acc[q].y);
            acc[q].z = fmaf(v, x4.z, acc[q].z);
            acc[q].w = fmaf(v, x4.w, acc[q].w);
        }
    }
    float* yp = out + (size_t)b * CDIM * NSEG + (size_t)c * NSEG + j0;
#pragma unroll
    for (int q = 0; q < 4; q++)
        __stcs((float4*)(yp + q * 1024), acc[q]);
}

// ---------------------------------------------------------------------------
extern "C" void kernel_launch(void* const* d_in, const int* in_sizes, int n_in,
                              void* d_out, int out_size) {
    const float* feats = (const float*)d_in[0];
    const float* gamma = (const float*)d_in[1];
    float* out = (float*)d_out;

    cudaFuncSetAttribute(gram_tc, cudaFuncAttributeMaxDynamicSharedMemorySize, GRAM_SMEM);
    gram_tc<<<dim3(GSPLIT, NB), 256, GRAM_SMEM>>>(feats);
    softmax_kernel<<<NB * CDIM, CDIM>>>(gamma);
    out_sparse<<<dim3(CDIM, 16, NB), 256>>>(feats, out);
}

// round 8
// speedup vs baseline: 9.3106x; 1.8405x over previous
#include <cuda_runtime.h>
#include <cuda_bf16.h>
#include <cstdint>

#define CDIM 256
#define NSEG 65536
#define NB 8
#define GSPLIT 16
#define KCHUNK (NSEG / GSPLIT)            // 4096
#define GCH 64
#define GNCH (KCHUNK / GCH)               // 64 chunks per gram CTA
#define BUFB (3 * 32768)                  // one H/M/L buffer set: 96 KB
#define GRAM_SMEM (1024 + 2 * BUFB)       // 197,632 B (double-buffered)

#if defined(__CUDA_ARCH_FEAT_SM103_ALL) || defined(__CUDA_ARCH_FEAT_SM100_ALL)
#define HAS_TC 1
#else
#define HAS_TC 0
#endif

__device__ float g_partial[(size_t)GSPLIT * NB * CDIM * CDIM]; // 32 MB
__device__ int   g_cnt[NB * CDIM];
__device__ int   g_sp_idx[NB * CDIM * CDIM];
__device__ float g_sp_val[NB * CDIM * CDIM];

#if HAS_TC
#define MBAR_WAIT(m, par) do { \
    uint32_t _m = (uint32_t)(m), _p = (uint32_t)(par), _d; \
    asm volatile("{\n\t.reg .pred p;\n\t" \
        "mbarrier.try_wait.parity.acquire.cta.shared::cta.b64 p, [%1], %2;\n\t" \
        "selp.b32 %0, 1, 0, p;\n\t}" : "=r"(_d) : "r"(_m), "r"(_p) : "memory"); \
    if (!_d) { \
        asm volatile("{\n\t.reg .pred P1;\n\t" \
            "WL_%=:\n\t" \
            "mbarrier.try_wait.parity.acquire.cta.shared::cta.b64 P1, [%0], %1, 0x989680;\n\t" \
            "@P1 bra.uni WD_%=;\n\tbra.uni WL_%=;\n\tWD_%=:\n\t}" \
            :: "r"(_m), "r"(_p) : "memory"); \
    } } while (0)
#endif

// ---------------------------------------------------------------------------
// Warp-specialized tcgen05 gram. 288 threads: warps 0-7 load+convert (3-way
// bf16 split, SW128 smem), warp 8 issues MMAs. Symmetry: accumulate
// D0 = rows 0-127 x cols 0-255 (N=256) and D1 = rows 128-255 x cols 128-255
// (N=128); the block (r>=128, c<128) is read transposed by softmax.
// full/empty mbarrier pairs per buffer decouple converters from MMA dispatch.
// ---------------------------------------------------------------------------
__global__ void __launch_bounds__(288, 1) gram_tc(const float* __restrict__ feats) {
#if HAS_TC
    extern __shared__ __align__(1024) char smem[];
    uint32_t sb;
    asm("{ .reg .u64 t; cvta.to.shared.u64 t, %1; cvt.u32.u64 %0, t; }" : "=r"(sb) : "l"(smem));
    const int tid = threadIdx.x, wid = tid >> 5;
    const float* X = feats + (size_t)blockIdx.y * CDIM * NSEG;
    const int k0 = blockIdx.x * KCHUNK;

    // mbarriers: empty0 @+8, empty1 @+16, full0 @+24, full1 @+32
    if (wid == 8) {
        asm volatile("tcgen05.alloc.cta_group::1.sync.aligned.shared::cta.b32 [%0], %1;"
                     :: "r"(sb), "r"(512u) : "memory");
        if ((tid & 31) == 0) {
            asm volatile("mbarrier.init.shared.b64 [%0], %1;" :: "r"(sb + 8),  "r"(1u)   : "memory");
            asm volatile("mbarrier.init.shared.b64 [%0], %1;" :: "r"(sb + 16), "r"(1u)   : "memory");
            asm volatile("mbarrier.init.shared.b64 [%0], %1;" :: "r"(sb + 24), "r"(256u) : "memory");
            asm volatile("mbarrier.init.shared.b64 [%0], %1;" :: "r"(sb + 32), "r"(256u) : "memory");
        }
    }
    __syncthreads();
    uint32_t tmem;
    asm volatile("ld.shared.b32 %0, [%1];" : "=r"(tmem) : "r"(sb));

    const uint64_t DBASE = 0x4000404000010000ull;  // SW128 K-major, v1, SBO=64, LBO=1
    const uint32_t IDESC0 = (1u << 4) | (1u << 7) | (1u << 10) | (32u << 17) | (8u << 24); // N=256
    const uint32_t IDESC1 = (1u << 4) | (1u << 7) | (1u << 10) | (16u << 17) | (8u << 24); // N=128

    if (wid < 8) {
        // ---- producer: load fp32, split to H/M/L bf16, signal full ----
        float4 rg[16];
#pragma unroll
        for (int p = 0; p < 16; p++) {
            int g = p * 256 + tid;
            rg[p] = *(const float4*)(X + (size_t)(g >> 4) * NSEG + k0 + (g & 15) * 4);
        }
        for (int i = 0; i < GNCH; i++) {
            const int s = i & 1;
            if (i >= 2) MBAR_WAIT(sb + 8 + s * 8, ((i - 2) >> 1) & 1);   // empty[s]
            const uint32_t H = sb + 1024 + s * BUFB, M = H + 32768, L = M + 32768;
#pragma unroll
            for (int p = 0; p < 16; p++) {
                int g = p * 256 + tid;
                float4 v = rg[p];
                __nv_bfloat162 h0 = __floats2bfloat162_rn(v.x, v.y);
                __nv_bfloat162 h1 = __floats2bfloat162_rn(v.z, v.w);
                float2 hf0 = __bfloat1622float2(h0), hf1 = __bfloat1622float2(h1);
                float r0x = v.x - hf0.x, r0y = v.y - hf0.y;
                float r1x = v.z - hf1.x, r1y = v.w - hf1.y;
                __nv_bfloat162 m0 = __floats2bfloat162_rn(r0x, r0y);
                __nv_bfloat162 m1 = __floats2bfloat162_rn(r1x, r1y);
                float2 mf0 = __bfloat1622float2(m0), mf1 = __bfloat1622float2(m1);
                __nv_bfloat162 l0 = __floats2bfloat162_rn(r0x - mf0.x, r0y - mf0.y);
                __nv_bfloat162 l1 = __floats2bfloat162_rn(r1x - mf1.x, r1y - mf1.y);
                uint32_t off = (uint32_t)((g >> 4) * 128 + (g & 15) * 8);
                off ^= (off >> 3) & 0x70;
                asm volatile("st.shared.v2.b32 [%0], {%1,%2};" :: "r"(H + off),
                             "r"(*(uint32_t*)&h0), "r"(*(uint32_t*)&h1) : "memory");
                asm volatile("st.shared.v2.b32 [%0], {%1,%2};" :: "r"(M + off),
                             "r"(*(uint32_t*)&m0), "r"(*(uint32_t*)&m1) : "memory");
                asm volatile("st.shared.v2.b32 [%0], {%1,%2};" :: "r"(L + off),
                             "r"(*(uint32_t*)&l0), "r"(*(uint32_t*)&l1) : "memory");
            }
            asm volatile("fence.proxy.async.shared::cta;" ::: "memory");
            asm volatile("mbarrier.arrive.shared.b64 _, [%0];" :: "r"(sb + 24 + s * 8) : "memory");
            if (i + 1 < GNCH) {
                const int kc = k0 + (i + 1) * GCH;
#pragma unroll
                for (int p = 0; p < 16; p++) {
                    int g = p * 256 + tid;
                    rg[p] = *(const float4*)(X + (size_t)(g >> 4) * NSEG + kc + (g & 15) * 4);
                }
            }
        }
    } else {
        // ---- MMA warp: wait full, issue 48 MMAs, commit to empty ----
        uint32_t is_e;
        asm volatile("{\n\t.reg .pred p;\n\telect.sync _|p, 0xFFFFFFFF;\n\t"
                     "selp.b32 %0, 1, 0, p;\n\t}" : "=r"(is_e));
        for (int i = 0; i < GNCH; i++) {
            const int s = i & 1;
            MBAR_WAIT(sb + 24 + s * 8, (i >> 1) & 1);                    // full[s]
            if (is_e) {
                const uint32_t H = sb + 1024 + s * BUFB, M = H + 32768, L = M + 32768;
                uint64_t dh = DBASE | ((H >> 4) & 0x3FFF);
                uint64_t dm = DBASE | ((M >> 4) & 0x3FFF);
                uint64_t dl = DBASE | ((L >> 4) & 0x3FFF);
#pragma unroll
                for (int ks = 0; ks < 4; ks++) {
                    uint64_t oh = dh + 2 * ks, om = dm + 2 * ks, ol = dl + 2 * ks;
                    bool f = (i == 0 && ks == 0);
#pragma unroll
                    for (int hf = 0; hf < 2; hf++) {
                        // hf=0: D0 rows 0-127 x cols 0-255 (N=256)
                        // hf=1: D1 rows 128-255 x cols 128-255 (N=128): A,B desc +1024
                        uint32_t d = tmem + hf * 256;
                        uint32_t idc = hf ? IDESC1 : IDESC0;
                        uint64_t ah = oh + hf * 1024, am = om + hf * 1024, al = ol + hf * 1024;
                        uint64_t bh = oh + hf * 1024, bm = om + hf * 1024, bl = ol + hf * 1024;
                        uint64_t av[6] = {ah, ah, am, ah, al, am};
                        uint64_t bv[6] = {bh, bm, bh, bl, bh, bm};
#pragma unroll
                        for (int t = 0; t < 6; t++) {
                            uint32_t en = (f && t == 0) ? 0u : 1u;
                            asm volatile("{\n\t.reg .pred p;\n\tsetp.ne.u32 p, %4, 0;\n\t"
                                "tcgen05.mma.cta_group::1.kind::f16 [%0], %1, %2, %3, {%5,%5,%5,%5}, p;\n\t}"
                                :: "r"(d), "l"(av[t]), "l"(bv[t]), "r"(idc), "r"(en), "r"(0u)
                                : "memory");
                        }
                    }
                }
                asm volatile("tcgen05.commit.cta_group::1.mbarrier::arrive::one.shared::cluster.b64 [%0];"
                             :: "r"(sb + 8 + s * 8) : "memory");
            }
        }
    }

    // drain final commits (empty[0] at chunk 62 -> parity 1, empty[1] at 63 -> parity 1)
    MBAR_WAIT(sb + 8,  ((GNCH - 2) >> 1) & 1);
    MBAR_WAIT(sb + 16, ((GNCH - 1) >> 1) & 1);
    asm volatile("tcgen05.fence::after_thread_sync;" ::: "memory");

    // epilogue: warps 0-3 store D0 (rows 0-127, cols 0-255),
    //           warps 4-7 store D1 (rows 128-255, cols 128-255)
    float* P = g_partial + ((size_t)blockIdx.x * NB + blockIdx.y) * (CDIM * CDIM);
    if (wid < 4) {
        const int row = wid * 32 + (tid & 31);
#pragma unroll 1
        for (int cg = 0; cg < 8; cg++) {
            uint32_t r[32];
            asm volatile("tcgen05.ld.sync.aligned.32x32b.x32.b32 "
                "{%0,%1,%2,%3,%4,%5,%6,%7,%8,%9,%10,%11,%12,%13,%14,%15,"
                "%16,%17,%18,%19,%20,%21,%22,%23,%24,%25,%26,%27,%28,%29,%30,%31}, [%32];"
                : "=r"(r[0]),"=r"(r[1]),"=r"(r[2]),"=r"(r[3]),"=r"(r[4]),"=r"(r[5]),
                  "=r"(r[6]),"=r"(r[7]),"=r"(r[8]),"=r"(r[9]),"=r"(r[10]),"=r"(r[11]),
                  "=r"(r[12]),"=r"(r[13]),"=r"(r[14]),"=r"(r[15]),"=r"(r[16]),"=r"(r[17]),
                  "=r"(r[18]),"=r"(r[19]),"=r"(r[20]),"=r"(r[21]),"=r"(r[22]),"=r"(r[23]),
                  "=r"(r[24]),"=r"(r[25]),"=r"(r[26]),"=r"(r[27]),"=r"(r[28]),"=r"(r[29]),
                  "=r"(r[30]),"=r"(r[31]) : "r"(tmem + cg * 32));
            asm volatile("tcgen05.wait::ld.sync.aligned;" ::: "memory");
            uint4* dst = (uint4*)(P + (size_t)row * CDIM + cg * 32);
#pragma unroll
            for (int q = 0; q < 8; q++)
                dst[q] = make_uint4(r[q * 4], r[q * 4 + 1], r[q * 4 + 2], r[q * 4 + 3]);
        }
    } else if (wid < 8) {
        const int row = 128 + (wid & 3) * 32 + (tid & 31);
#pragma unroll 1
        for (int cg = 0; cg < 4; cg++) {
            uint32_t r[32];
            asm volatile("tcgen05.ld.sync.aligned.32x32b.x32.b32 "
                "{%0,%1,%2,%3,%4,%5,%6,%7,%8,%9,%10,%11,%12,%13,%14,%15,"
                "%16,%17,%18,%19,%20,%21,%22,%23,%24,%25,%26,%27,%28,%29,%30,%31}, [%32];"
                : "=r"(r[0]),"=r"(r[1]),"=r"(r[2]),"=r"(r[3]),"=r"(r[4]),"=r"(r[5]),
                  "=r"(r[6]),"=r"(r[7]),"=r"(r[8]),"=r"(r[9]),"=r"(r[10]),"=r"(r[11]),
                  "=r"(r[12]),"=r"(r[13]),"=r"(r[14]),"=r"(r[15]),"=r"(r[16]),"=r"(r[17]),
                  "=r"(r[18]),"=r"(r[19]),"=r"(r[20]),"=r"(r[21]),"=r"(r[22]),"=r"(r[23]),
                  "=r"(r[24]),"=r"(r[25]),"=r"(r[26]),"=r"(r[27]),"=r"(r[28]),"=r"(r[29]),
                  "=r"(r[30]),"=r"(r[31]) : "r"(tmem + 256 + cg * 32));
            asm volatile("tcgen05.wait::ld.sync.aligned;" ::: "memory");
            uint4* dst = (uint4*)(P + (size_t)row * CDIM + 128 + cg * 32);
#pragma unroll
            for (int q = 0; q < 8; q++)
                dst[q] = make_uint4(r[q * 4], r[q * 4 + 1], r[q * 4 + 2], r[q * 4 + 3]);
        }
    }
    __syncthreads();
    if (wid == 8)
        asm volatile("tcgen05.dealloc.cta_group::1.sync.aligned.b32 %0, %1;"
                     :: "r"(tmem), "r"(512u));
#endif
}

// ---------------------------------------------------------------------------
// Softmax + exact-sparsity extraction. Partials are symmetric: the block
// (r>=128, d<128) was not written; read its transpose instead.
// ---------------------------------------------------------------------------
__global__ void softmax_kernel(const float* __restrict__ gamma) {
    const int b = blockIdx.x >> 8, r = blockIdx.x & 255;
    const int d = threadIdx.x;
    const bool direct = (r < 128) || (d >= 128);
    const int rr = direct ? r : d;
    const int dd = direct ? d : r;
    const size_t base = (size_t)b * (CDIM * CDIM) + (size_t)rr * CDIM + dd;

    float e = 0.f;
#pragma unroll
    for (int s = 0; s < GSPLIT; s++)
        e += g_partial[(size_t)s * (NB * CDIM * CDIM) + base];

    __shared__ float red[CDIM];
    __shared__ int wb[9];
    red[d] = e;
    __syncthreads();
    for (int s = 128; s > 0; s >>= 1) {
        if (d < s) red[d] = fminf(red[d], red[d + s]);
        __syncthreads();
    }
    float minv = red[0];
    __syncthreads();
    float v = expf(minv - e);
    red[d] = v;
    __syncthreads();
    for (int s = 128; s > 0; s >>= 1) {
        if (d < s) red[d] += red[d + s];
        __syncthreads();
    }
    float S = red[0];

    bool keep = (e - minv) < 100.0f;
    unsigned msk = __ballot_sync(0xffffffffu, keep);
    int lane = d & 31, w = d >> 5;
    if (lane == 0) wb[w] = __popc(msk);
    __syncthreads();
    if (d == 0) {
        int acc = 0;
        for (int t = 0; t < 8; t++) { int x = wb[t]; wb[t] = acc; acc += x; }
        wb[8] = acc;
    }
    __syncthreads();
    const int row = blockIdx.x;
    if (keep) {
        int pos = wb[w] + __popc(msk & ((1u << lane) - 1));
        g_sp_idx[row * CDIM + pos] = d;
        g_sp_val[row * CDIM + pos] = gamma[0] * v / S;
    }
    if (d == 0) g_cnt[row] = wb[8];
}

// ---------------------------------------------------------------------------
// Sparse out: y[c,j] = sum_k val[c,k] * x[d_k, j] + x[c,j]  (evict-first Y)
// ---------------------------------------------------------------------------
__global__ void __launch_bounds__(256) out_sparse(const float* __restrict__ feats,
                                                  float* __restrict__ out) {
    const int c = blockIdx.x, b = blockIdx.z;
    const int row = b * CDIM + c;
    const float* Xb = feats + (size_t)b * CDIM * NSEG;
    const int j0 = blockIdx.y * 4096 + threadIdx.x * 4;

    float4 acc[4];
#pragma unroll
    for (int q = 0; q < 4; q++)
        acc[q] = *(const float4*)(Xb + (size_t)c * NSEG + j0 + q * 1024);

    const int cnt = g_cnt[row];
    for (int k = 0; k < cnt; k++) {
        const int dd = g_sp_idx[row * CDIM + k];
        const float v = g_sp_val[row * CDIM + k];
        const float* xp = Xb + (size_t)dd * NSEG + j0;
#pragma unroll
        for (int q = 0; q < 4; q++) {
            float4 x4 = *(const float4*)(xp + q * 1024);
            acc[q].x = fmaf(v, x4.x, acc[q].x);
            acc[q].y = fmaf(v, x4.y, acc[q].y);
            acc[q].z = fmaf(v, x4.z, acc[q].z);
            acc[q].w = fmaf(v, x4.w, acc[q].w);
        }
    }
    float* yp = out + (size_t)b * CDIM * NSEG + (size_t)c * NSEG + j0;
#pragma unroll
    for (int q = 0; q < 4; q++)
        __stcs((float4*)(yp + q * 1024), acc[q]);
}

// ---------------------------------------------------------------------------
extern "C" void kernel_launch(void* const* d_in, const int* in_sizes, int n_in,
                              void* d_out, int out_size) {
    const float* feats = (const float*)d_in[0];
    const float* gamma = (const float*)d_in[1];
    float* out = (float*)d_out;

    cudaFuncSetAttribute(gram_tc, cudaFuncAttributeMaxDynamicSharedMemorySize, GRAM_SMEM);
    gram_tc<<<dim3(GSPLIT, NB), 288, GRAM_SMEM>>>(feats);
    softmax_kernel<<<NB * CDIM, CDIM>>>(gamma);
    out_sparse<<<dim3(CDIM, 16, NB), 256>>>(feats, out);
}